// round 15
// baseline (speedup 1.0000x reference)
#include <cuda_runtime.h>
#include <cuda_fp16.h>
#include <cstdint>

#define B_SZ   1024
#define IN_SZ  128
#define OUT_SZ 10000
#define OUTP   10112            // row pitch (158*64); tile 157 is dead padding
#define KCEN   16
#define NTEFF  157              // effective n-tiles of 64 (cols 0..10047)
#define NT1    37               // head chunk: 37*8 = 296 CTAs = exactly 1 wave
#define SSC    64.0f

#define LDA 136                 // A pitch (halves): 128 + 8
#define LDB 72                  // B pitch (halves): 64 + 8
#define ATILE (128*LDA)
#define BTILE (128*LDB)
#define SMEM_HALVES (ATILE + 2*BTILE)
#define SMEM_BYTES  (SMEM_HALVES*2)      // 71680

// ---------------- device scratch ----------------
__device__ float4  g_xh4[(B_SZ*IN_SZ)/8];                      // 256 KB fp16
__device__ float4  g_wh4[((size_t)KCEN*IN_SZ*OUTP)/8];         // 41.4 MB fp16 (normalized)
__device__ __half2 g_cosh[((size_t)B_SZ*OUTP)/2 + 256];        // 20.7 MB fp16 cos (+pad)
__device__ float   g_cosfa[B_SZ], g_sinfa[B_SZ], g_costhr[B_SZ];
__device__ float   g_loss[B_SZ], g_corr[B_SZ];

// ---------------- prep_x ------------------------------------------------------
__global__ void prep_x_kernel(const float* __restrict__ x,
                              const float* __restrict__ factor) {
    int b = blockIdx.x, f = threadIdx.x;     // 128 threads
    float v = x[b*IN_SZ + f];
    float s = v*v;
    #pragma unroll
    for (int o = 16; o; o >>= 1) s += __shfl_xor_sync(0xffffffffu, s, o);
    __shared__ float ws[4];
    if ((f & 31) == 0) ws[f >> 5] = s;
    __syncthreads();
    float tot = ws[0] + ws[1] + ws[2] + ws[3];
    float rinv = 1.f / fmaxf(sqrtf(tot), 1e-12f);
    ((__half*)g_xh4)[b*IN_SZ + f] = __float2half(v * rinv);
    if (f == 0) {
        float fa = powf(1.5f, factor[b] * (1.f/12.f)) * 0.5f;
        float cfa = cosf(fa);
        g_cosfa[b] = cfa;
        g_sinfa[b] = sinf(fa);
        g_costhr[b] = -cfa;                  // cos(pi - fa)
    }
}

// ---------------- prep_w: 2-pass, column-range parameterized ------------------
__global__ void prep_w_kernel(const float* __restrict__ w, int o_base, int ncols) {
    int idx = blockIdx.x*blockDim.x + threadIdx.x;
    int k = idx / ncols, ol = idx - k*ncols;
    int o = o_base + ol;
    __half* wh = (__half*)g_wh4;
    size_t base = (size_t)k*IN_SZ*OUTP + o;
    if (o >= OUT_SZ) {
        for (int f = 0; f < IN_SZ; f++) wh[base + (size_t)f*OUTP] = __float2half(0.f);
        return;
    }
    const float* col = w + (size_t)k*IN_SZ*OUT_SZ + o;
    float s = 0.f;
    #pragma unroll 8
    for (int f = 0; f < IN_SZ; f++) { float v = col[(size_t)f*OUT_SZ]; s += v*v; }
    float rinv = 1.f / fmaxf(sqrtf(s), 1e-12f);
    #pragma unroll 8
    for (int f = 0; f < IN_SZ; f++)
        wh[base + (size_t)f*OUTP] = __float2half(col[(size_t)f*OUT_SZ] * rinv);
}

// ---------------- GEMM helpers -------------------------------------------------
__device__ __forceinline__ void cp_async16(uint32_t saddr, const void* gptr) {
    asm volatile("cp.async.cg.shared.global [%0], [%1], 16;\n" :: "r"(saddr), "l"(gptr));
}
#define CP_COMMIT() asm volatile("cp.async.commit_group;\n")
#define CP_WAIT1()  asm volatile("cp.async.wait_group 1;\n")

#define LDSM_X4(r0,r1,r2,r3,addr) \
    asm volatile("ldmatrix.sync.aligned.m8n8.x4.shared.b16 {%0,%1,%2,%3}, [%4];" \
        : "=r"(r0),"=r"(r1),"=r"(r2),"=r"(r3) : "r"(addr))
#define LDSM_X4_T(r0,r1,r2,r3,addr) \
    asm volatile("ldmatrix.sync.aligned.m8n8.x4.trans.shared.b16 {%0,%1,%2,%3}, [%4];" \
        : "=r"(r0),"=r"(r1),"=r"(r2),"=r"(r3) : "r"(addr))
// fp16-accumulate MMA: D,C = 2 b32 regs (rows r / r+8, cols c,c+1 packed)
#define MMA16816H(c0,c1,a0,a1,a2,a3,b0,b1) \
    asm volatile("mma.sync.aligned.m16n8k16.row.col.f16.f16.f16.f16 " \
        "{%0,%1},{%2,%3,%4,%5},{%6,%7},{%0,%1};" \
        : "+r"(c0),"+r"(c1) \
        : "r"(a0),"r"(a1),"r"(a2),"r"(a3),"r"(b0),"r"(b1))

// B tile: 128 k-rows x 64 n-cols = 8 chunks of 16B per row
__device__ __forceinline__ void load_b_tile(__half* Bs, const __half* wh,
                                            int tid, int n0, int kc, int buf) {
    int chunk = tid & 7, r0 = tid >> 3;          // 32 rows per pass of 256 thr
    const __half* src = wh + (size_t)kc*IN_SZ*OUTP + n0;
    __half* dst = Bs + buf*BTILE;
    #pragma unroll
    for (int it = 0; it < 4; it++) {
        int row = it*32 + r0;
        cp_async16((uint32_t)__cvta_generic_to_shared(dst + row*LDB + chunk*8),
                   src + (size_t)row*OUTP + chunk*8);
    }
}

// ---------------- main GEMM: 128x64 tile, 2 CTA/SM, f16-accum MMA (r11) -------
__global__ void __launch_bounds__(256, 2) gemm_kernel(int nt0) {
    extern __shared__ __half sm[];
    __half* As = sm;
    __half* Bs = sm + ATILE;
    const __half* xh = (const __half*)g_xh4;
    const __half* wh = (const __half*)g_wh4;

    int tid = threadIdx.x;
    int n0 = (nt0 + blockIdx.x) * 64;
    int m0 = blockIdx.y * 128;

    {   // A tile: 128x128 halves
        int chunk = tid & 15, r0 = tid >> 4;
        #pragma unroll
        for (int it = 0; it < 8; it++) {
            int row = it*16 + r0;
            cp_async16((uint32_t)__cvta_generic_to_shared(As + row*LDA + chunk*8),
                       xh + (size_t)(m0 + row)*IN_SZ + chunk*8);
        }
    }
    load_b_tile(Bs, wh, tid, n0, 0, 0);
    CP_COMMIT();

    int wid = tid >> 5, lane = tid & 31;
    int wm = wid & 3, wn = wid >> 2;             // 4 m-warps x 2 n-warps (32x32 each)

    uint32_t smem_u32v = (uint32_t)__cvta_generic_to_shared(sm);
    uint32_t aA = smem_u32v + ((wm*32 + (lane & 15))*LDA + (lane >> 4)*8)*2;
    uint32_t aB = smem_u32v + ATILE*2 + ((lane & 15)*LDB + wn*32 + (lane >> 4)*8)*2;

    __half2 mx2[2][4][2];
    const __half2 NEGH = __floats2half2_rn(-65504.f, -65504.f);
    #pragma unroll
    for (int i = 0; i < 2; i++)
        #pragma unroll
        for (int j = 0; j < 4; j++) { mx2[i][j][0] = NEGH; mx2[i][j][1] = NEGH; }

    for (int kc = 0; kc < KCEN; kc++) {
        int buf = kc & 1;
        if (kc < KCEN-1) load_b_tile(Bs, wh, tid, n0, kc+1, buf ^ 1);
        CP_COMMIT();
        CP_WAIT1();
        __syncthreads();

        uint32_t bbase = aB + buf*BTILE*2;

        uint32_t acc[2][4][2];
        #pragma unroll
        for (int i = 0; i < 2; i++)
            #pragma unroll
            for (int j = 0; j < 4; j++) { acc[i][j][0] = 0u; acc[i][j][1] = 0u; }

        uint32_t a[2][2][4], bq[2][4][2];
        #pragma unroll
        for (int mt = 0; mt < 2; mt++)
            LDSM_X4(a[0][mt][0], a[0][mt][1], a[0][mt][2], a[0][mt][3],
                    aA + mt*16*LDA*2);
        #pragma unroll
        for (int p = 0; p < 2; p++)
            LDSM_X4_T(bq[0][2*p][0], bq[0][2*p][1], bq[0][2*p+1][0], bq[0][2*p+1][1],
                      bbase + p*32);

        #pragma unroll
        for (int ks = 0; ks < 8; ks++) {
            int cur = ks & 1, nxt = cur ^ 1;
            if (ks < 7) {
                #pragma unroll
                for (int mt = 0; mt < 2; mt++)
                    LDSM_X4(a[nxt][mt][0], a[nxt][mt][1], a[nxt][mt][2], a[nxt][mt][3],
                            aA + mt*16*LDA*2 + (ks+1)*32);
                #pragma unroll
                for (int p = 0; p < 2; p++)
                    LDSM_X4_T(bq[nxt][2*p][0], bq[nxt][2*p][1],
                              bq[nxt][2*p+1][0], bq[nxt][2*p+1][1],
                              bbase + (ks+1)*16*LDB*2 + p*32);
            }
            #pragma unroll
            for (int mt = 0; mt < 2; mt++)
                #pragma unroll
                for (int nt = 0; nt < 4; nt++)
                    MMA16816H(acc[mt][nt][0], acc[mt][nt][1],
                              a[cur][mt][0], a[cur][mt][1], a[cur][mt][2], a[cur][mt][3],
                              bq[cur][nt][0], bq[cur][nt][1]);
        }

        #pragma unroll
        for (int i = 0; i < 2; i++)
            #pragma unroll
            for (int j = 0; j < 4; j++) {
                mx2[i][j][0] = __hmax2(mx2[i][j][0], *(__half2*)&acc[i][j][0]);
                mx2[i][j][1] = __hmax2(mx2[i][j][1], *(__half2*)&acc[i][j][1]);
            }
        __syncthreads();
    }

    int rbase = m0 + wm*32 + (lane >> 2);
    int cbase = n0 + wn*32 + (lane & 3)*2;
    #pragma unroll
    for (int mt = 0; mt < 2; mt++)
        #pragma unroll
        for (int nt = 0; nt < 4; nt++) {
            int r = rbase + mt*16, c = cbase + nt*8;
            g_cosh[((size_t)r*OUTP + c) >> 1]     = mx2[mt][nt][0];
            g_cosh[((size_t)(r+8)*OUTP + c) >> 1] = mx2[mt][nt][1];
        }
}

// ---------------- epilogue: uint4 loads (8 cols each), 2-phase -----------------
__global__ void __launch_bounds__(256) epi_kernel(const int* __restrict__ label) {
    int r = blockIdx.x, t = threadIdx.x;     // 256 threads, 5 uint4 each
    const uint4* row4 = (const uint4*)(g_cosh + (size_t)r*(OUTP/2));
    int lab = label[r];
    float cfa = g_cosfa[r], sfa = g_sinfa[r], cthr = g_costhr[r];

    __shared__ float s_mn[8], s_sum[8];
    __shared__ float s_lab;

    // phase 0: batched 16B loads (cols >=10000 loaded but never used)
    uint4 v4[5];
    #pragma unroll
    for (int j = 0; j < 5; j++)
        v4[j] = row4[j*256 + t];

    const float CLO = -1.0f + 1e-6f, CHI = 1.0f - 1e-6f;
    const int NV4 = OUT_SZ / 8;              // 1250 full uint4 per row, exact
    float mnon = -3.0e38f;

    #pragma unroll
    for (int j = 0; j < 5; j++) {
        int idx = j*256 + t;
        if (idx < NV4) {
            const __half2* h = (const __half2*)&v4[j];
            int obase = idx*8;
            #pragma unroll
            for (int e = 0; e < 4; e++) {
                float c0 = fminf(fmaxf(__low2float(h[e]),  CLO), CHI);
                float c1 = fminf(fmaxf(__high2float(h[e]), CLO), CHI);
                int o0 = obase + e*2;
                if (o0 == lab) {
                    s_lab = (c0 >= cthr)
                        ? (c0*cfa - sqrtf(fmaxf(1.f - c0*c0, 0.f))*sfa) * SSC
                        : c0 * SSC;
                } else mnon = fmaxf(mnon, c0 * SSC);
                if (o0 + 1 == lab) {
                    s_lab = (c1 >= cthr)
                        ? (c1*cfa - sqrtf(fmaxf(1.f - c1*c1, 0.f))*sfa) * SSC
                        : c1 * SSC;
                } else mnon = fmaxf(mnon, c1 * SSC);
            }
        }
    }
    #pragma unroll
    for (int o = 16; o; o >>= 1) mnon = fmaxf(mnon, __shfl_xor_sync(0xffffffffu, mnon, o));
    if ((t & 31) == 0) s_mn[t >> 5] = mnon;
    __syncthreads();
    float Mn = fmaxf(fmaxf(fmaxf(s_mn[0], s_mn[1]), fmaxf(s_mn[2], s_mn[3])),
                     fmaxf(fmaxf(s_mn[4], s_mn[5]), fmaxf(s_mn[6], s_mn[7])));
    float llab = s_lab;
    float M = fmaxf(Mn, llab);

    float s = 0.f;
    #pragma unroll
    for (int j = 0; j < 5; j++) {
        int idx = j*256 + t;
        if (idx < NV4) {
            const __half2* h = (const __half2*)&v4[j];
            int obase = idx*8;
            #pragma unroll
            for (int e = 0; e < 4; e++) {
                float c0 = fminf(fmaxf(__low2float(h[e]),  CLO), CHI);
                float c1 = fminf(fmaxf(__high2float(h[e]), CLO), CHI);
                int o0 = obase + e*2;
                float l0 = (o0     == lab) ? llab : c0 * SSC;
                float l1 = (o0 + 1 == lab) ? llab : c1 * SSC;
                s += __expf(l0 - M) + __expf(l1 - M);
            }
        }
    }
    #pragma unroll
    for (int o = 16; o; o >>= 1) s += __shfl_xor_sync(0xffffffffu, s, o);
    if ((t & 31) == 0) s_sum[t >> 5] = s;
    __syncthreads();
    if (t == 0) {
        float S = s_sum[0]+s_sum[1]+s_sum[2]+s_sum[3]
                + s_sum[4]+s_sum[5]+s_sum[6]+s_sum[7];
        g_loss[r] = logf(S) + M - llab;
        g_corr[r] = (llab > Mn) ? 1.f : 0.f;
    }
}

// ---------------- final reduction ------------------------------------------
__global__ void fin_kernel(float* __restrict__ out) {
    int t = threadIdx.x;                     // 1024 threads
    __shared__ float sl[1024], sc[1024];
    sl[t] = g_loss[t]; sc[t] = g_corr[t];
    __syncthreads();
    for (int st = 512; st > 0; st >>= 1) {
        if (t < st) { sl[t] += sl[t+st]; sc[t] += sc[t+st]; }
        __syncthreads();
    }
    if (t == 0) {
        out[0] = sl[0] * (1.f/1024.f);
        out[1] = sc[0] * (100.f/1024.f);
    }
}

// ---------------- launch: fork/join overlap of prep_w tail with GEMM head ---
extern "C" void kernel_launch(void* const* d_in, const int* in_sizes, int n_in,
                              void* d_out, int out_size) {
    const float* x      = (const float*)d_in[0];
    const float* factor = (const float*)d_in[1];
    const int*   label  = (const int*)  d_in[2];
    const float* w      = (const float*)d_in[3];
    float* out = (float*)d_out;

    cudaFuncSetAttribute(gemm_kernel, cudaFuncAttributeMaxDynamicSharedMemorySize, SMEM_BYTES);

    cudaStream_t s1;
    cudaStreamCreateWithFlags(&s1, cudaStreamNonBlocking);
    cudaEvent_t eFork, eJoin;
    cudaEventCreateWithFlags(&eFork, cudaEventDisableTiming);
    cudaEventCreateWithFlags(&eJoin, cudaEventDisableTiming);

    // fork: prep_w tail (cols NT1*64 .. 10047) on s1, concurrent with head
    cudaEventRecord(eFork, 0);
    cudaStreamWaitEvent(s1, eFork, 0);
    {
        int ncols2 = (NTEFF - NT1) * 64;              // 7680 (incl. pad cols)
        prep_w_kernel<<<(KCEN*ncols2)/256, 256, 0, s1>>>(w, NT1*64, ncols2);
    }

    // head on default stream: 37*8 = 296 CTAs = exactly one machine wave
    prep_x_kernel<<<B_SZ, 128>>>(x, factor);
    prep_w_kernel<<<(KCEN*NT1*64)/256, 256>>>(w, 0, NT1*64);
    gemm_kernel<<<dim3(NT1, B_SZ/128), 256, SMEM_BYTES>>>(0);

    // join: remaining GEMM needs prep_w tail
    cudaEventRecord(eJoin, s1);
    cudaStreamWaitEvent(0, eJoin, 0);
    gemm_kernel<<<dim3(NTEFF - NT1, B_SZ/128), 256, SMEM_BYTES>>>(NT1);

    epi_kernel<<<B_SZ, 256>>>(label);
    fin_kernel<<<1, 1024>>>(out);

    cudaStreamDestroy(s1);
    cudaEventDestroy(eFork);
    cudaEventDestroy(eJoin);
}

// round 16
// speedup vs baseline: 1.0313x; 1.0313x over previous
#include <cuda_runtime.h>
#include <cuda_fp16.h>
#include <cstdint>

#define B_SZ   1024
#define IN_SZ  128
#define OUT_SZ 10000
#define OUTP   10112            // row pitch (158*64); tile 157 is dead padding
#define KCEN   16
#define NTEFF  157              // effective n-tiles of 64 (cols 0..10047)
#define NT1    37               // head chunk
#define SSC    64.0f

#define LDA 136                 // A pitch (halves): 128 + 8
#define LDB 72                  // B pitch (halves): 64 + 8
#define ATILE (128*LDA)
#define BTILE (128*LDB)
#define SMEM_HALVES (ATILE + 2*BTILE)
#define SMEM_BYTES  (SMEM_HALVES*2)      // 71680 -> 3 CTAs/SM fits 228KB

// ---------------- device scratch ----------------
__device__ float4  g_xh4[(B_SZ*IN_SZ)/8];                      // 256 KB fp16
__device__ float4  g_wh4[((size_t)KCEN*IN_SZ*OUTP)/8];         // 41.4 MB fp16 (normalized)
__device__ __half2 g_cosh[((size_t)B_SZ*OUTP)/2 + 256];        // 20.7 MB fp16 cos (+pad)
__device__ float   g_cosfa[B_SZ], g_sinfa[B_SZ], g_costhr[B_SZ];
__device__ float   g_loss[B_SZ], g_corr[B_SZ];

// ---------------- prep_x ------------------------------------------------------
__global__ void prep_x_kernel(const float* __restrict__ x,
                              const float* __restrict__ factor) {
    int b = blockIdx.x, f = threadIdx.x;     // 128 threads
    float v = x[b*IN_SZ + f];
    float s = v*v;
    #pragma unroll
    for (int o = 16; o; o >>= 1) s += __shfl_xor_sync(0xffffffffu, s, o);
    __shared__ float ws[4];
    if ((f & 31) == 0) ws[f >> 5] = s;
    __syncthreads();
    float tot = ws[0] + ws[1] + ws[2] + ws[3];
    float rinv = 1.f / fmaxf(sqrtf(tot), 1e-12f);
    ((__half*)g_xh4)[b*IN_SZ + f] = __float2half(v * rinv);
    if (f == 0) {
        float fa = powf(1.5f, factor[b] * (1.f/12.f)) * 0.5f;
        float cfa = cosf(fa);
        g_cosfa[b] = cfa;
        g_sinfa[b] = sinf(fa);
        g_costhr[b] = -cfa;                  // cos(pi - fa)
    }
}

// ---------------- prep_w: 2-pass, column-range parameterized ------------------
__global__ void prep_w_kernel(const float* __restrict__ w, int o_base, int ncols) {
    int idx = blockIdx.x*blockDim.x + threadIdx.x;
    int k = idx / ncols, ol = idx - k*ncols;
    int o = o_base + ol;
    __half* wh = (__half*)g_wh4;
    size_t base = (size_t)k*IN_SZ*OUTP + o;
    if (o >= OUT_SZ) {
        for (int f = 0; f < IN_SZ; f++) wh[base + (size_t)f*OUTP] = __float2half(0.f);
        return;
    }
    const float* col = w + (size_t)k*IN_SZ*OUT_SZ + o;
    float s = 0.f;
    #pragma unroll 8
    for (int f = 0; f < IN_SZ; f++) { float v = col[(size_t)f*OUT_SZ]; s += v*v; }
    float rinv = 1.f / fmaxf(sqrtf(s), 1e-12f);
    #pragma unroll 8
    for (int f = 0; f < IN_SZ; f++)
        wh[base + (size_t)f*OUTP] = __float2half(col[(size_t)f*OUT_SZ] * rinv);
}

// ---------------- GEMM helpers -------------------------------------------------
__device__ __forceinline__ void cp_async16(uint32_t saddr, const void* gptr) {
    asm volatile("cp.async.cg.shared.global [%0], [%1], 16;\n" :: "r"(saddr), "l"(gptr));
}
#define CP_COMMIT() asm volatile("cp.async.commit_group;\n")
#define CP_WAIT1()  asm volatile("cp.async.wait_group 1;\n")

#define LDSM_X4(r0,r1,r2,r3,addr) \
    asm volatile("ldmatrix.sync.aligned.m8n8.x4.shared.b16 {%0,%1,%2,%3}, [%4];" \
        : "=r"(r0),"=r"(r1),"=r"(r2),"=r"(r3) : "r"(addr))
#define LDSM_X4_T(r0,r1,r2,r3,addr) \
    asm volatile("ldmatrix.sync.aligned.m8n8.x4.trans.shared.b16 {%0,%1,%2,%3}, [%4];" \
        : "=r"(r0),"=r"(r1),"=r"(r2),"=r"(r3) : "r"(addr))
// fp16-accumulate MMA: D,C = 2 b32 regs (rows r / r+8, cols c,c+1 packed)
#define MMA16816H(c0,c1,a0,a1,a2,a3,b0,b1) \
    asm volatile("mma.sync.aligned.m16n8k16.row.col.f16.f16.f16.f16 " \
        "{%0,%1},{%2,%3,%4,%5},{%6,%7},{%0,%1};" \
        : "+r"(c0),"+r"(c1) \
        : "r"(a0),"r"(a1),"r"(a2),"r"(a3),"r"(b0),"r"(b1))

// B tile: 128 k-rows x 64 n-cols = 8 chunks of 16B per row
__device__ __forceinline__ void load_b_tile(__half* Bs, const __half* wh,
                                            int tid, int n0, int kc, int buf) {
    int chunk = tid & 7, r0 = tid >> 3;          // 32 rows per pass of 256 thr
    const __half* src = wh + (size_t)kc*IN_SZ*OUTP + n0;
    __half* dst = Bs + buf*BTILE;
    #pragma unroll
    for (int it = 0; it < 4; it++) {
        int row = it*32 + r0;
        cp_async16((uint32_t)__cvta_generic_to_shared(dst + row*LDB + chunk*8),
                   src + (size_t)row*OUTP + chunk*8);
    }
}

// ---------------- main GEMM: 128x64 tile, 3 CTA/SM, f16-accum MMA -------------
__global__ void __launch_bounds__(256, 3) gemm_kernel(int nt0) {
    extern __shared__ __half sm[];
    __half* As = sm;
    __half* Bs = sm + ATILE;
    const __half* xh = (const __half*)g_xh4;
    const __half* wh = (const __half*)g_wh4;

    int tid = threadIdx.x;
    int n0 = (nt0 + blockIdx.x) * 64;
    int m0 = blockIdx.y * 128;

    {   // A tile: 128x128 halves
        int chunk = tid & 15, r0 = tid >> 4;
        #pragma unroll
        for (int it = 0; it < 8; it++) {
            int row = it*16 + r0;
            cp_async16((uint32_t)__cvta_generic_to_shared(As + row*LDA + chunk*8),
                       xh + (size_t)(m0 + row)*IN_SZ + chunk*8);
        }
    }
    load_b_tile(Bs, wh, tid, n0, 0, 0);
    CP_COMMIT();

    int wid = tid >> 5, lane = tid & 31;
    int wm = wid & 3, wn = wid >> 2;             // 4 m-warps x 2 n-warps (32x32 each)

    uint32_t smem_u32v = (uint32_t)__cvta_generic_to_shared(sm);
    uint32_t aA = smem_u32v + ((wm*32 + (lane & 15))*LDA + (lane >> 4)*8)*2;
    uint32_t aB = smem_u32v + ATILE*2 + ((lane & 15)*LDB + wn*32 + (lane >> 4)*8)*2;

    __half2 mx2[2][4][2];
    const __half2 NEGH = __floats2half2_rn(-65504.f, -65504.f);
    #pragma unroll
    for (int i = 0; i < 2; i++)
        #pragma unroll
        for (int j = 0; j < 4; j++) { mx2[i][j][0] = NEGH; mx2[i][j][1] = NEGH; }

    for (int kc = 0; kc < KCEN; kc++) {
        int buf = kc & 1;
        if (kc < KCEN-1) load_b_tile(Bs, wh, tid, n0, kc+1, buf ^ 1);
        CP_COMMIT();
        CP_WAIT1();
        __syncthreads();

        uint32_t bbase = aB + buf*BTILE*2;

        uint32_t acc[2][4][2];
        #pragma unroll
        for (int i = 0; i < 2; i++)
            #pragma unroll
            for (int j = 0; j < 4; j++) { acc[i][j][0] = 0u; acc[i][j][1] = 0u; }

        #pragma unroll
        for (int ks = 0; ks < 8; ks++) {
            uint32_t a[2][4];
            #pragma unroll
            for (int mt = 0; mt < 2; mt++)
                LDSM_X4(a[mt][0], a[mt][1], a[mt][2], a[mt][3],
                        aA + mt*16*LDA*2 + ks*32);
            uint32_t bq[4][2];
            #pragma unroll
            for (int p = 0; p < 2; p++)
                LDSM_X4_T(bq[2*p][0], bq[2*p][1], bq[2*p+1][0], bq[2*p+1][1],
                          bbase + ks*16*LDB*2 + p*32);
            #pragma unroll
            for (int mt = 0; mt < 2; mt++)
                #pragma unroll
                for (int nt = 0; nt < 4; nt++)
                    MMA16816H(acc[mt][nt][0], acc[mt][nt][1],
                              a[mt][0], a[mt][1], a[mt][2], a[mt][3],
                              bq[nt][0], bq[nt][1]);
        }

        #pragma unroll
        for (int i = 0; i < 2; i++)
            #pragma unroll
            for (int j = 0; j < 4; j++) {
                mx2[i][j][0] = __hmax2(mx2[i][j][0], *(__half2*)&acc[i][j][0]);
                mx2[i][j][1] = __hmax2(mx2[i][j][1], *(__half2*)&acc[i][j][1]);
            }
        __syncthreads();
    }

    int rbase = m0 + wm*32 + (lane >> 2);
    int cbase = n0 + wn*32 + (lane & 3)*2;
    #pragma unroll
    for (int mt = 0; mt < 2; mt++)
        #pragma unroll
        for (int nt = 0; nt < 4; nt++) {
            int r = rbase + mt*16, c = cbase + nt*8;
            g_cosh[((size_t)r*OUTP + c) >> 1]     = mx2[mt][nt][0];
            g_cosh[((size_t)(r+8)*OUTP + c) >> 1] = mx2[mt][nt][1];
        }
}

// ---------------- epilogue: uint4 loads (8 cols each), 2-phase -----------------
__global__ void __launch_bounds__(256) epi_kernel(const int* __restrict__ label) {
    int r = blockIdx.x, t = threadIdx.x;     // 256 threads, 5 uint4 each
    const uint4* row4 = (const uint4*)(g_cosh + (size_t)r*(OUTP/2));
    int lab = label[r];
    float cfa = g_cosfa[r], sfa = g_sinfa[r], cthr = g_costhr[r];

    __shared__ float s_mn[8], s_sum[8];
    __shared__ float s_lab;

    uint4 v4[5];
    #pragma unroll
    for (int j = 0; j < 5; j++)
        v4[j] = row4[j*256 + t];

    const float CLO = -1.0f + 1e-6f, CHI = 1.0f - 1e-6f;
    const int NV4 = OUT_SZ / 8;              // 1250 full uint4 per row, exact
    float mnon = -3.0e38f;

    #pragma unroll
    for (int j = 0; j < 5; j++) {
        int idx = j*256 + t;
        if (idx < NV4) {
            const __half2* h = (const __half2*)&v4[j];
            int obase = idx*8;
            #pragma unroll
            for (int e = 0; e < 4; e++) {
                float c0 = fminf(fmaxf(__low2float(h[e]),  CLO), CHI);
                float c1 = fminf(fmaxf(__high2float(h[e]), CLO), CHI);
                int o0 = obase + e*2;
                if (o0 == lab) {
                    s_lab = (c0 >= cthr)
                        ? (c0*cfa - sqrtf(fmaxf(1.f - c0*c0, 0.f))*sfa) * SSC
                        : c0 * SSC;
                } else mnon = fmaxf(mnon, c0 * SSC);
                if (o0 + 1 == lab) {
                    s_lab = (c1 >= cthr)
                        ? (c1*cfa - sqrtf(fmaxf(1.f - c1*c1, 0.f))*sfa) * SSC
                        : c1 * SSC;
                } else mnon = fmaxf(mnon, c1 * SSC);
            }
        }
    }
    #pragma unroll
    for (int o = 16; o; o >>= 1) mnon = fmaxf(mnon, __shfl_xor_sync(0xffffffffu, mnon, o));
    if ((t & 31) == 0) s_mn[t >> 5] = mnon;
    __syncthreads();
    float Mn = fmaxf(fmaxf(fmaxf(s_mn[0], s_mn[1]), fmaxf(s_mn[2], s_mn[3])),
                     fmaxf(fmaxf(s_mn[4], s_mn[5]), fmaxf(s_mn[6], s_mn[7])));
    float llab = s_lab;
    float M = fmaxf(Mn, llab);

    float s = 0.f;
    #pragma unroll
    for (int j = 0; j < 5; j++) {
        int idx = j*256 + t;
        if (idx < NV4) {
            const __half2* h = (const __half2*)&v4[j];
            int obase = idx*8;
            #pragma unroll
            for (int e = 0; e < 4; e++) {
                float c0 = fminf(fmaxf(__low2float(h[e]),  CLO), CHI);
                float c1 = fminf(fmaxf(__high2float(h[e]), CLO), CHI);
                int o0 = obase + e*2;
                float l0 = (o0     == lab) ? llab : c0 * SSC;
                float l1 = (o0 + 1 == lab) ? llab : c1 * SSC;
                s += __expf(l0 - M) + __expf(l1 - M);
            }
        }
    }
    #pragma unroll
    for (int o = 16; o; o >>= 1) s += __shfl_xor_sync(0xffffffffu, s, o);
    if ((t & 31) == 0) s_sum[t >> 5] = s;
    __syncthreads();
    if (t == 0) {
        float S = s_sum[0]+s_sum[1]+s_sum[2]+s_sum[3]
                + s_sum[4]+s_sum[5]+s_sum[6]+s_sum[7];
        g_loss[r] = logf(S) + M - llab;
        g_corr[r] = (llab > Mn) ? 1.f : 0.f;
    }
}

// ---------------- final reduction ------------------------------------------
__global__ void fin_kernel(float* __restrict__ out) {
    int t = threadIdx.x;                     // 1024 threads
    __shared__ float sl[1024], sc[1024];
    sl[t] = g_loss[t]; sc[t] = g_corr[t];
    __syncthreads();
    for (int st = 512; st > 0; st >>= 1) {
        if (t < st) { sl[t] += sl[t+st]; sc[t] += sc[t+st]; }
        __syncthreads();
    }
    if (t == 0) {
        out[0] = sl[0] * (1.f/1024.f);
        out[1] = sc[0] * (100.f/1024.f);
    }
}

// ---------------- launch: fork/join overlap of prep_w tail with GEMM head ---
extern "C" void kernel_launch(void* const* d_in, const int* in_sizes, int n_in,
                              void* d_out, int out_size) {
    const float* x      = (const float*)d_in[0];
    const float* factor = (const float*)d_in[1];
    const int*   label  = (const int*)  d_in[2];
    const float* w      = (const float*)d_in[3];
    float* out = (float*)d_out;

    cudaFuncSetAttribute(gemm_kernel, cudaFuncAttributeMaxDynamicSharedMemorySize, SMEM_BYTES);

    cudaStream_t s1;
    cudaStreamCreateWithFlags(&s1, cudaStreamNonBlocking);
    cudaEvent_t eFork, eJoin;
    cudaEventCreateWithFlags(&eFork, cudaEventDisableTiming);
    cudaEventCreateWithFlags(&eJoin, cudaEventDisableTiming);

    // fork: prep_w tail (cols NT1*64 .. 10047) on s1, concurrent with head
    cudaEventRecord(eFork, 0);
    cudaStreamWaitEvent(s1, eFork, 0);
    {
        int ncols2 = (NTEFF - NT1) * 64;              // 7680 (incl. pad cols)
        prep_w_kernel<<<(KCEN*ncols2)/256, 256, 0, s1>>>(w, NT1*64, ncols2);
    }

    // head on default stream
    prep_x_kernel<<<B_SZ, 128>>>(x, factor);
    prep_w_kernel<<<(KCEN*NT1*64)/256, 256>>>(w, 0, NT1*64);
    gemm_kernel<<<dim3(NT1, B_SZ/128), 256, SMEM_BYTES>>>(0);

    // join: remaining GEMM needs prep_w tail
    cudaEventRecord(eJoin, s1);
    cudaStreamWaitEvent(0, eJoin, 0);
    gemm_kernel<<<dim3(NTEFF - NT1, B_SZ/128), 256, SMEM_BYTES>>>(NT1);

    epi_kernel<<<B_SZ, 256>>>(label);
    fin_kernel<<<1, 1024>>>(out);

    cudaStreamDestroy(s1);
    cudaEventDestroy(eFork);
    cudaEventDestroy(eJoin);
}